// round 6
// baseline (speedup 1.0000x reference)
#include <cuda_runtime.h>
#include <cstdint>
#include <cstddef>

// Problem constants
#define Bc 256
#define Dc 256
#define Kc 1024
#define Ec 16
#define KSPLIT 8
#define KH (Kc / KSPLIT)   // 128 codes per argmin block

// Output offsets (floats) within d_out, in reference return order:
// cw_embed (B, D*E), one_hot (B, D, K), new_codebook (D, K, E), new_ema (D, K)
static const size_t OFF_EMB = 0;
static const size_t OFF_OH  = (size_t)Bc * Dc * Ec;                    // 1,048,576
static const size_t OFF_NCB = OFF_OH + (size_t)Bc * Dc * Kc;           // 68,157,440
static const size_t OFF_NEC = OFF_NCB + (size_t)Dc * Kc * Ec;          // 72,351,744

// Scratch
__device__ unsigned long long g_key[KSPLIT * Dc * Bc];   // packed argmin keys
__device__ int g_sidx[Bc * Dc];                          // final argmin, [b][d]

// ---- packed f32x2 helpers (Blackwell) ----
__device__ __forceinline__ unsigned long long pk2(float a, float b) {
    unsigned long long r;
    asm("mov.b64 %0,{%1,%2};" : "=l"(r) : "f"(a), "f"(b));
    return r;
}
__device__ __forceinline__ void upk2(unsigned long long v, float& a, float& b) {
    asm("mov.b64 {%0,%1},%2;" : "=f"(a), "=f"(b) : "l"(v));
}
__device__ __forceinline__ unsigned long long f2fma(unsigned long long a, unsigned long long b, unsigned long long c) {
    unsigned long long d;
    asm("fma.rn.f32x2 %0,%1,%2,%3;" : "=l"(d) : "l"(a), "l"(b), "l"(c));
    return d;
}
__device__ __forceinline__ unsigned long long f2add(unsigned long long a, unsigned long long b) {
    unsigned long long d;
    asm("add.rn.f32x2 %0,%1,%2;" : "=l"(d) : "l"(a), "l"(b));
    return d;
}
__device__ __forceinline__ unsigned long long f2mul(unsigned long long a, unsigned long long b) {
    unsigned long long d;
    asm("mul.rn.f32x2 %0,%1,%2;" : "=l"(d) : "l"(a), "l"(b));
    return d;
}

// Map float to an order-preserving uint (no NaNs expected).
__device__ __forceinline__ unsigned int orderable(float f) {
    unsigned int u = __float_as_uint(f);
    return (u & 0x80000000u) ? ~u : (u | 0x80000000u);
}

// =====================================================================
// Kernel A: argmin over one K-chunk. grid = (Dc, KSPLIT), block = 256.
// Static smem: 8 KB packed codebook chunk + 0.5 KB c2 -> 3 CTAs/SM.
// =====================================================================
__global__ void __launch_bounds__(256, 3)
vq_argmin(const float* __restrict__ cw_q,
          const float* __restrict__ codebook)
{
    // cpack[(k>>1)*32 + e*2 + (k&1)] = codebook[d][sp*KH + k][e]
    __shared__ float cpack[KH * Ec];         // 8 KB
    __shared__ float c2f[KH];                // 0.5 KB (pairs adjacent)

    const int d  = blockIdx.x;
    const int sp = blockIdx.y;
    const int t  = threadIdx.x;
    const float* cb = codebook + ((size_t)d * Kc + (size_t)sp * KH) * Ec;

    // stage + pack the codebook chunk (KH*Ec = 2048 floats, 8 per thread)
    #pragma unroll
    for (int i = t; i < KH * Ec; i += 256) {
        float v = cb[i];
        int k = i >> 4, e = i & 15;
        cpack[(k >> 1) * 32 + e * 2 + (k & 1)] = v;
    }
    __syncthreads();

    // per-k squared norms
    if (t < KH) {
        const int k = t;
        const float* cp = cpack + (k >> 1) * 32 + (k & 1);
        float s = 0.f;
        #pragma unroll
        for (int e = 0; e < 16; e++) { float c = cp[e * 2]; s += c * c; }
        c2f[k] = s;
    }
    __syncthreads();

    // load x for batch b = t; build packed duplicates and x2
    const int b = t;
    const float* xp = cw_q + (size_t)b * (Dc * Ec) + (size_t)d * Ec;
    unsigned long long xx[16];
    float x2 = 0.f;
    #pragma unroll
    for (int q = 0; q < 4; q++) {
        float4 v = ((const float4*)xp)[q];
        x2 += v.x * v.x; x2 += v.y * v.y; x2 += v.z * v.z; x2 += v.w * v.w;
        xx[4 * q + 0] = pk2(v.x, v.x);
        xx[4 * q + 1] = pk2(v.y, v.y);
        xx[4 * q + 2] = pk2(v.z, v.z);
        xx[4 * q + 3] = pk2(v.w, v.w);
    }

    const unsigned long long X2 = pk2(x2, x2);
    const unsigned long long NT = pk2(-2.0f, -2.0f);
    const unsigned long long ZZ = pk2(0.0f, 0.0f);
    const unsigned long long* c2p = (const unsigned long long*)c2f;

    float best = 3.4e38f;
    int bidx = 0;

    const ulonglong2* cp2 = (const ulonglong2*)cpack;  // 8 ulonglong2 per k-pair row
    #pragma unroll 2
    for (int p = 0; p < KH / 2; p++) {
        const ulonglong2* row = cp2 + p * 8;
        // 4 independent accumulator chains (ILP=4, depth 4)
        unsigned long long a0 = ZZ, a1 = ZZ, a2 = ZZ, a3 = ZZ;
        #pragma unroll
        for (int j = 0; j < 4; j++) {
            ulonglong2 u = row[2 * j];
            ulonglong2 w = row[2 * j + 1];
            a0 = f2fma(xx[4 * j + 0], u.x, a0);
            a1 = f2fma(xx[4 * j + 1], u.y, a1);
            a2 = f2fma(xx[4 * j + 2], w.x, a2);
            a3 = f2fma(xx[4 * j + 3], w.y, a3);
        }
        unsigned long long dot2  = f2add(f2add(a0, a1), f2add(a2, a3));
        unsigned long long s2    = f2add(X2, c2p[p]);          // x2 + c2 (ref order)
        unsigned long long dist2 = f2add(s2, f2mul(NT, dot2)); // (x2+c2) + (-2*xc)
        float d0, d1;
        upk2(dist2, d0, d1);
        float cd = d0; int ck = 2 * p;
        if (d1 < d0) { cd = d1; ck = 2 * p + 1; }   // first-min semantics
        if (cd < best) { best = cd; bidx = ck; }
    }

    // pack (orderable dist, global k): min over keys == first-occurrence argmin
    unsigned long long key = ((unsigned long long)orderable(best) << 32)
                           | (unsigned long long)(sp * KH + bidx);
    g_key[((size_t)sp * Dc + d) * Bc + b] = key;
}

// =====================================================================
// Kernel B1: embed / histogram / EMA outputs. grid = Dc, block = 256.
// Dynamic smem: acc 64 KB + scnt 4 KB = 69632 B -> 3 CTAs/SM (one wave).
// =====================================================================
#define B1_SMEM (65536 + 4096)

extern __shared__ unsigned char smemB[];

__global__ void __launch_bounds__(256)
vq_outputs(const float* __restrict__ cw_q,
           const float* __restrict__ codebook,
           const float* __restrict__ ema,
           float* __restrict__ out)
{
    float* acc = (float*)smemB;                       // [Kc][Ec]
    int* scnt  = (int*)(smemB + 65536);               // [Kc]

    const int d = blockIdx.x;
    const int t = threadIdx.x;
    const int b = t;

    // combine split keys -> argmin index
    unsigned long long key = g_key[((size_t)0 * Dc + d) * Bc + b];
    #pragma unroll
    for (int sp = 1; sp < KSPLIT; sp++) {
        unsigned long long k2 = g_key[((size_t)sp * Dc + d) * Bc + b];
        if (k2 < key) key = k2;
    }
    const int idx = (int)(key & 0xFFFFFFFFull);
    g_sidx[(size_t)b * Dc + d] = idx;

    // zero accumulator + histogram
    {
        float4 z = make_float4(0.f, 0.f, 0.f, 0.f);
        float4* av = (float4*)acc;
        #pragma unroll
        for (int i = t; i < (Kc * Ec) / 4; i += 256) av[i] = z;
        #pragma unroll
        for (int i = t; i < Kc; i += 256) scnt[i] = 0;
    }
    __syncthreads();

    // histogram + scatter x
    atomicAdd(&scnt[idx], 1);

    const float* xp = cw_q + (size_t)b * (Dc * Ec) + (size_t)d * Ec;
    float xf[16];
    {
        float4 v0 = ((const float4*)xp)[0];
        float4 v1 = ((const float4*)xp)[1];
        float4 v2 = ((const float4*)xp)[2];
        float4 v3 = ((const float4*)xp)[3];
        xf[0]=v0.x; xf[1]=v0.y; xf[2]=v0.z; xf[3]=v0.w;
        xf[4]=v1.x; xf[5]=v1.y; xf[6]=v1.z; xf[7]=v1.w;
        xf[8]=v2.x; xf[9]=v2.y; xf[10]=v2.z; xf[11]=v2.w;
        xf[12]=v3.x; xf[13]=v3.y; xf[14]=v3.z; xf[15]=v3.w;
    }
    #pragma unroll
    for (int e = 0; e < 16; e++) atomicAdd(&acc[idx * Ec + e], xf[e]);

    // cw_embed[b, d*16..] = codebook[d][idx]  (gmem gather, L2-resident)
    {
        const float4* ce = (const float4*)(codebook + ((size_t)d * Kc + idx) * Ec);
        float* dst = out + OFF_EMB + (size_t)b * (Dc * Ec) + (size_t)d * Ec;
        #pragma unroll
        for (int q = 0; q < 4; q++) ((float4*)dst)[q] = __ldg(ce + q);
    }
    __syncthreads();   // acc/scnt complete

    const float* emad = ema + (size_t)d * Kc;

    // new_ema_counts
    #pragma unroll
    for (int k = t; k < Kc; k += 256)
        out[OFF_NEC + (size_t)d * Kc + k] = 0.999f * emad[k] + 0.001f * (float)scnt[k];

    // new_codebook
    {
        const float* cbd = codebook + (size_t)d * (Kc * Ec);
        #pragma unroll
        for (int i = t; i < Kc * Ec; i += 256) {
            int k = i >> 4;
            float nc = 0.999f * cbd[i] + 0.001f * (acc[i] / (emad[k] + 1e-6f));
            out[OFF_NCB + (size_t)d * (Kc * Ec) + i] = nc;
        }
    }
}

// =====================================================================
// Kernel B2: one_hot streaming writer. grid = (Bc, 4), block = 256.
// Each block writes out_oh[b, q*64 .. q*64+63, :]  (256 KB contiguous).
// =====================================================================
#define DCHUNK 64

__global__ void __launch_bounds__(256)
vq_onehot(float* __restrict__ out)
{
    __shared__ int sidxs[DCHUNK];

    const int b = blockIdx.x;
    const int q = blockIdx.y;
    const int t = threadIdx.x;

    if (t < DCHUNK) sidxs[t] = g_sidx[(size_t)b * Dc + q * DCHUNK + t];
    __syncthreads();

    float* base = out + OFF_OH + (size_t)b * (Dc * Kc) + (size_t)q * DCHUNK * Kc;
    const int kbase = t * 4;   // thread t covers K elements [4t, 4t+3]

    #pragma unroll 4
    for (int dd = 0; dd < DCHUNK; dd++) {
        int idx = sidxs[dd];               // warp-uniform broadcast
        float4 v;
        v.x = (idx == kbase + 0) ? 1.0f : 0.0f;
        v.y = (idx == kbase + 1) ? 1.0f : 0.0f;
        v.z = (idx == kbase + 2) ? 1.0f : 0.0f;
        v.w = (idx == kbase + 3) ? 1.0f : 0.0f;
        ((float4*)(base + (size_t)dd * Kc))[t] = v;
    }
}

extern "C" void kernel_launch(void* const* d_in, const int* in_sizes, int n_in,
                              void* d_out, int out_size)
{
    const float* cw_q     = (const float*)d_in[0];
    const float* codebook = (const float*)d_in[1];
    const float* ema      = (const float*)d_in[2];
    float* out            = (float*)d_out;

    cudaFuncSetAttribute(vq_outputs, cudaFuncAttributeMaxDynamicSharedMemorySize, B1_SMEM);

    vq_argmin<<<dim3(Dc, KSPLIT), 256>>>(cw_q, codebook);
    vq_outputs<<<Dc, 256, B1_SMEM>>>(cw_q, codebook, ema, out);
    vq_onehot<<<dim3(Bc, 4), 256>>>(out);
}

// round 7
// speedup vs baseline: 1.3897x; 1.3897x over previous
#include <cuda_runtime.h>
#include <cstdint>
#include <cstddef>

// Problem constants
#define Bc 256
#define Dc 256
#define Kc 1024
#define Ec 16
#define KSPLIT 8
#define KH (Kc / KSPLIT)   // 128 codes per argmin block

// Output offsets (floats) within d_out, in reference return order:
// cw_embed (B, D*E), one_hot (B, D, K), new_codebook (D, K, E), new_ema (D, K)
static const size_t OFF_EMB = 0;
static const size_t OFF_OH  = (size_t)Bc * Dc * Ec;                    // 1,048,576
static const size_t OFF_NCB = OFF_OH + (size_t)Bc * Dc * Kc;           // 68,157,440
static const size_t OFF_NEC = OFF_NCB + (size_t)Dc * Kc * Ec;          // 72,351,744

// One_hot zero-fill: 67,108,864 floats / 2048 blocks = 32768 floats per block.
#define ZCHUNK 32768

// Scratch: per-(split, d, b) packed argmin key (non-atomic, owner-written).
__device__ unsigned long long g_key[KSPLIT * Dc * Bc];

// ---- packed f32x2 helpers (Blackwell) ----
__device__ __forceinline__ unsigned long long pk2(float a, float b) {
    unsigned long long r;
    asm("mov.b64 %0,{%1,%2};" : "=l"(r) : "f"(a), "f"(b));
    return r;
}
__device__ __forceinline__ void upk2(unsigned long long v, float& a, float& b) {
    asm("mov.b64 {%0,%1},%2;" : "=f"(a), "=f"(b) : "l"(v));
}
__device__ __forceinline__ unsigned long long f2fma(unsigned long long a, unsigned long long b, unsigned long long c) {
    unsigned long long d;
    asm("fma.rn.f32x2 %0,%1,%2,%3;" : "=l"(d) : "l"(a), "l"(b), "l"(c));
    return d;
}
__device__ __forceinline__ unsigned long long f2add(unsigned long long a, unsigned long long b) {
    unsigned long long d;
    asm("add.rn.f32x2 %0,%1,%2;" : "=l"(d) : "l"(a), "l"(b));
    return d;
}

// Map float to an order-preserving uint (no NaNs expected).
__device__ __forceinline__ unsigned int orderable(float f) {
    unsigned int u = __float_as_uint(f);
    return (u & 0x80000000u) ? ~u : (u | 0x80000000u);
}

// =====================================================================
// Kernel A: argmin over one K-chunk + one_hot zero-fill.
// grid = (Dc, KSPLIT), block = 128. Thread t handles batches t and t+128.
// Per k-pair: 8 LDS.128 feed 32 FFMA2 (8 independent chains).
// Zero stores interleaved every 8 k-pairs to spread DRAM writes.
// =====================================================================
__global__ void __launch_bounds__(128, 4)
vq_argmin_zf(const float* __restrict__ cw_q,
             const float* __restrict__ codebook,
             float* __restrict__ out)
{
    // cpack[(k>>1)*32 + e*2 + (k&1)] = codebook[d][sp*KH + k][e]
    __shared__ float cpack[KH * Ec];         // 8 KB
    __shared__ float c2f[KH];                // 0.5 KB (code pairs adjacent)

    const int d  = blockIdx.x;
    const int sp = blockIdx.y;
    const int t  = threadIdx.x;
    const float* cb = codebook + ((size_t)d * Kc + (size_t)sp * KH) * Ec;

    // stage + pack codebook chunk (512 float4s, 4 per thread)
    #pragma unroll
    for (int i = t; i < (KH * Ec) / 4; i += 128) {
        float4 v = ((const float4*)cb)[i];
        int k  = i >> 2;          // 4 float4 per code
        int e0 = (i & 3) * 4;
        float* dstp = &cpack[(k >> 1) * 32 + (k & 1)];
        dstp[(e0 + 0) * 2] = v.x;
        dstp[(e0 + 1) * 2] = v.y;
        dstp[(e0 + 2) * 2] = v.z;
        dstp[(e0 + 3) * 2] = v.w;
    }
    __syncthreads();

    // per-k squared norms (KH == 128 == blockDim.x)
    {
        const int k = t;
        const float* cp = cpack + (k >> 1) * 32 + (k & 1);
        float s = 0.f;
        #pragma unroll
        for (int e = 0; e < 16; e++) { float c = cp[e * 2]; s += c * c; }
        c2f[k] = s;
    }
    __syncthreads();

    // load x for two batches; pack (-2x) duplicates (exactly -2 * original chain)
    unsigned long long xx0[16], xx1[16];
    float x20 = 0.f, x21 = 0.f;
    {
        const float* xp0 = cw_q + (size_t)t * (Dc * Ec) + (size_t)d * Ec;
        const float* xp1 = cw_q + (size_t)(t + 128) * (Dc * Ec) + (size_t)d * Ec;
        #pragma unroll
        for (int q = 0; q < 4; q++) {
            float4 v = ((const float4*)xp0)[q];
            x20 += v.x * v.x; x20 += v.y * v.y; x20 += v.z * v.z; x20 += v.w * v.w;
            xx0[4*q+0] = pk2(-2.0f*v.x, -2.0f*v.x);
            xx0[4*q+1] = pk2(-2.0f*v.y, -2.0f*v.y);
            xx0[4*q+2] = pk2(-2.0f*v.z, -2.0f*v.z);
            xx0[4*q+3] = pk2(-2.0f*v.w, -2.0f*v.w);
        }
        #pragma unroll
        for (int q = 0; q < 4; q++) {
            float4 v = ((const float4*)xp1)[q];
            x21 += v.x * v.x; x21 += v.y * v.y; x21 += v.z * v.z; x21 += v.w * v.w;
            xx1[4*q+0] = pk2(-2.0f*v.x, -2.0f*v.x);
            xx1[4*q+1] = pk2(-2.0f*v.y, -2.0f*v.y);
            xx1[4*q+2] = pk2(-2.0f*v.z, -2.0f*v.z);
            xx1[4*q+3] = pk2(-2.0f*v.w, -2.0f*v.w);
        }
    }

    const unsigned long long X20 = pk2(x20, x20);
    const unsigned long long X21 = pk2(x21, x21);
    const unsigned long long ZZ  = pk2(0.0f, 0.0f);
    const unsigned long long* c2p = (const unsigned long long*)c2f;
    const ulonglong2* cp2 = (const ulonglong2*)cpack;   // 8 per k-pair row

    float best0 = 3.4e38f, best1 = 3.4e38f;
    int bi0 = 0, bi1 = 0;

    // zero-fill target for this block
    float4* z4 = (float4*)(out + OFF_OH + (size_t)(d * KSPLIT + sp) * ZCHUNK);
    const float4 zf4 = make_float4(0.f, 0.f, 0.f, 0.f);

    // KH/2 = 64 k-pairs = 8 segments x 8 pairs; 8 zero-float4s per seg per thread
    for (int seg = 0; seg < 8; seg++) {
        #pragma unroll 2
        for (int pp = 0; pp < 8; pp++) {
            const int p = seg * 8 + pp;
            const ulonglong2* row = cp2 + p * 8;
            unsigned long long a0 = ZZ, a1 = ZZ, a2 = ZZ, a3 = ZZ;
            unsigned long long b0 = ZZ, b1 = ZZ, b2 = ZZ, b3 = ZZ;
            #pragma unroll
            for (int j = 0; j < 4; j++) {
                ulonglong2 u = row[2 * j];
                ulonglong2 w = row[2 * j + 1];
                a0 = f2fma(xx0[4*j+0], u.x, a0);
                a1 = f2fma(xx0[4*j+1], u.y, a1);
                a2 = f2fma(xx0[4*j+2], w.x, a2);
                a3 = f2fma(xx0[4*j+3], w.y, a3);
                b0 = f2fma(xx1[4*j+0], u.x, b0);
                b1 = f2fma(xx1[4*j+1], u.y, b1);
                b2 = f2fma(xx1[4*j+2], w.x, b2);
                b3 = f2fma(xx1[4*j+3], w.y, b3);
            }
            unsigned long long c2v = c2p[p];
            // batch 0: dist = (x2 + c2) + sum((-2x)*c)   [bit-identical to ref path]
            {
                unsigned long long dot  = f2add(f2add(a0, a1), f2add(a2, a3));
                unsigned long long dist = f2add(f2add(X20, c2v), dot);
                float d0, d1; upk2(dist, d0, d1);
                float cd = d0; int ck = 2 * p;
                if (d1 < d0) { cd = d1; ck = 2 * p + 1; }
                if (cd < best0) { best0 = cd; bi0 = ck; }
            }
            // batch 1
            {
                unsigned long long dot  = f2add(f2add(b0, b1), f2add(b2, b3));
                unsigned long long dist = f2add(f2add(X21, c2v), dot);
                float d0, d1; upk2(dist, d0, d1);
                float cd = d0; int ck = 2 * p;
                if (d1 < d0) { cd = d1; ck = 2 * p + 1; }
                if (cd < best1) { best1 = cd; bi1 = ck; }
            }
        }
        // interleaved one_hot zero-fill: 8 float4 per thread per segment
        #pragma unroll
        for (int j = 0; j < 8; j++)
            __stcs(&z4[seg * 1024 + j * 128 + t], zf4);
    }

    // pack (orderable dist, global k): min over keys == first-occurrence argmin
    const size_t kb = ((size_t)sp * Dc + d) * Bc;
    g_key[kb + t] = ((unsigned long long)orderable(best0) << 32)
                  | (unsigned long long)(sp * KH + bi0);
    g_key[kb + t + 128] = ((unsigned long long)orderable(best1) << 32)
                        | (unsigned long long)(sp * KH + bi1);
}

// =====================================================================
// Kernel B: combine + all remaining outputs. grid = Dc, block = 256.
// Dynamic smem: acc 64 KB + scnt 4 KB = 69632 B -> 3 CTAs/SM (one wave).
// Also scatters the 1.0 entries into the (pre-zeroed) one_hot tensor.
// =====================================================================
#define B1_SMEM (65536 + 4096)

extern __shared__ unsigned char smemB[];

__global__ void __launch_bounds__(256)
vq_outputs(const float* __restrict__ cw_q,
           const float* __restrict__ codebook,
           const float* __restrict__ ema,
           float* __restrict__ out)
{
    float* acc = (float*)smemB;                       // [Kc][Ec]
    int* scnt  = (int*)(smemB + 65536);               // [Kc]

    const int d = blockIdx.x;
    const int t = threadIdx.x;
    const int b = t;

    // combine split keys -> argmin index
    unsigned long long key = g_key[((size_t)0 * Dc + d) * Bc + b];
    #pragma unroll
    for (int sp = 1; sp < KSPLIT; sp++) {
        unsigned long long k2 = g_key[((size_t)sp * Dc + d) * Bc + b];
        if (k2 < key) key = k2;
    }
    const int idx = (int)(key & 0xFFFFFFFFull);

    // one_hot scatter: set the single 1.0 for (b, d) (slab pre-zeroed by K1)
    out[OFF_OH + (size_t)b * (Dc * Kc) + (size_t)d * Kc + idx] = 1.0f;

    // zero accumulator + histogram
    {
        float4 z = make_float4(0.f, 0.f, 0.f, 0.f);
        float4* av = (float4*)acc;
        #pragma unroll
        for (int i = t; i < (Kc * Ec) / 4; i += 256) av[i] = z;
        #pragma unroll
        for (int i = t; i < Kc; i += 256) scnt[i] = 0;
    }
    __syncthreads();

    // histogram + scatter x
    atomicAdd(&scnt[idx], 1);

    const float* xp = cw_q + (size_t)b * (Dc * Ec) + (size_t)d * Ec;
    float xf[16];
    {
        float4 v0 = ((const float4*)xp)[0];
        float4 v1 = ((const float4*)xp)[1];
        float4 v2 = ((const float4*)xp)[2];
        float4 v3 = ((const float4*)xp)[3];
        xf[0]=v0.x; xf[1]=v0.y; xf[2]=v0.z; xf[3]=v0.w;
        xf[4]=v1.x; xf[5]=v1.y; xf[6]=v1.z; xf[7]=v1.w;
        xf[8]=v2.x; xf[9]=v2.y; xf[10]=v2.z; xf[11]=v2.w;
        xf[12]=v3.x; xf[13]=v3.y; xf[14]=v3.z; xf[15]=v3.w;
    }
    #pragma unroll
    for (int e = 0; e < 16; e++) atomicAdd(&acc[idx * Ec + e], xf[e]);

    // cw_embed[b, d*16..] = codebook[d][idx]  (gmem gather, L2-resident)
    {
        const float4* ce = (const float4*)(codebook + ((size_t)d * Kc + idx) * Ec);
        float* dst = out + OFF_EMB + (size_t)b * (Dc * Ec) + (size_t)d * Ec;
        #pragma unroll
        for (int q = 0; q < 4; q++) ((float4*)dst)[q] = __ldg(ce + q);
    }
    __syncthreads();   // acc/scnt complete

    const float* emad = ema + (size_t)d * Kc;

    // new_ema_counts
    #pragma unroll
    for (int k = t; k < Kc; k += 256)
        out[OFF_NEC + (size_t)d * Kc + k] = 0.999f * emad[k] + 0.001f * (float)scnt[k];

    // new_codebook
    {
        const float* cbd = codebook + (size_t)d * (Kc * Ec);
        #pragma unroll
        for (int i = t; i < Kc * Ec; i += 256) {
            int k = i >> 4;
            float nc = 0.999f * cbd[i] + 0.001f * (acc[i] / (emad[k] + 1e-6f));
            out[OFF_NCB + (size_t)d * (Kc * Ec) + i] = nc;
        }
    }
}

extern "C" void kernel_launch(void* const* d_in, const int* in_sizes, int n_in,
                              void* d_out, int out_size)
{
    const float* cw_q     = (const float*)d_in[0];
    const float* codebook = (const float*)d_in[1];
    const float* ema      = (const float*)d_in[2];
    float* out            = (float*)d_out;

    cudaFuncSetAttribute(vq_outputs, cudaFuncAttributeMaxDynamicSharedMemorySize, B1_SMEM);

    vq_argmin_zf<<<dim3(Dc, KSPLIT), 128>>>(cw_q, codebook, out);
    vq_outputs<<<Dc, 256, B1_SMEM>>>(cw_q, codebook, ema, out);
}

// round 9
// speedup vs baseline: 1.5624x; 1.1243x over previous
#include <cuda_runtime.h>
#include <cstdint>
#include <cstddef>

// Problem constants
#define Bc 256
#define Dc 256
#define Kc 1024
#define Ec 16
#define KSPLIT 8
#define KH (Kc / KSPLIT)   // 128 codes per argmin block

// Output offsets (floats) within d_out, in reference return order:
// cw_embed (B, D*E), one_hot (B, D, K), new_codebook (D, K, E), new_ema (D, K)
static const size_t OFF_EMB = 0;
static const size_t OFF_OH  = (size_t)Bc * Dc * Ec;                    // 1,048,576
static const size_t OFF_NCB = OFF_OH + (size_t)Bc * Dc * Kc;           // 68,157,440
static const size_t OFF_NEC = OFF_NCB + (size_t)Dc * Kc * Ec;          // 72,351,744

// One_hot zero-fill: 67,108,864 floats / 2048 blocks = 32768 floats per block.
#define ZCHUNK 32768

// Scratch
__device__ unsigned long long g_key[KSPLIT * Dc * Bc];  // packed argmin keys
__device__ int g_sidx_db[Dc * Bc];                      // argmin, [d][b]
__device__ int g_sidx_bd[Bc * Dc];                      // argmin, [b][d]

// ---- packed f32x2 helpers (Blackwell) ----
__device__ __forceinline__ unsigned long long pk2(float a, float b) {
    unsigned long long r;
    asm("mov.b64 %0,{%1,%2};" : "=l"(r) : "f"(a), "f"(b));
    return r;
}
__device__ __forceinline__ void upk2(unsigned long long v, float& a, float& b) {
    asm("mov.b64 {%0,%1},%2;" : "=f"(a), "=f"(b) : "l"(v));
}
__device__ __forceinline__ unsigned long long f2fma(unsigned long long a, unsigned long long b, unsigned long long c) {
    unsigned long long d;
    asm("fma.rn.f32x2 %0,%1,%2,%3;" : "=l"(d) : "l"(a), "l"(b), "l"(c));
    return d;
}
__device__ __forceinline__ unsigned long long f2add(unsigned long long a, unsigned long long b) {
    unsigned long long d;
    asm("add.rn.f32x2 %0,%1,%2;" : "=l"(d) : "l"(a), "l"(b));
    return d;
}

// Map float to an order-preserving uint (no NaNs expected).
__device__ __forceinline__ unsigned int orderable(float f) {
    unsigned int u = __float_as_uint(f);
    return (u & 0x80000000u) ? ~u : (u | 0x80000000u);
}

// =====================================================================
// Kernel 1: argmin over one K-chunk + one_hot zero-fill. (unchanged)
// grid = (Dc, KSPLIT), block = 128. Thread t handles batches t and t+128.
// =====================================================================
__global__ void __launch_bounds__(128, 4)
vq_argmin_zf(const float* __restrict__ cw_q,
             const float* __restrict__ codebook,
             float* __restrict__ out)
{
    __shared__ float cpack[KH * Ec];         // 8 KB
    __shared__ float c2f[KH];                // 0.5 KB (code pairs adjacent)

    const int d  = blockIdx.x;
    const int sp = blockIdx.y;
    const int t  = threadIdx.x;
    const float* cb = codebook + ((size_t)d * Kc + (size_t)sp * KH) * Ec;

    #pragma unroll
    for (int i = t; i < (KH * Ec) / 4; i += 128) {
        float4 v = ((const float4*)cb)[i];
        int k  = i >> 2;
        int e0 = (i & 3) * 4;
        float* dstp = &cpack[(k >> 1) * 32 + (k & 1)];
        dstp[(e0 + 0) * 2] = v.x;
        dstp[(e0 + 1) * 2] = v.y;
        dstp[(e0 + 2) * 2] = v.z;
        dstp[(e0 + 3) * 2] = v.w;
    }
    __syncthreads();

    {
        const int k = t;
        const float* cp = cpack + (k >> 1) * 32 + (k & 1);
        float s = 0.f;
        #pragma unroll
        for (int e = 0; e < 16; e++) { float c = cp[e * 2]; s += c * c; }
        c2f[k] = s;
    }
    __syncthreads();

    unsigned long long xx0[16], xx1[16];
    float x20 = 0.f, x21 = 0.f;
    {
        const float* xp0 = cw_q + (size_t)t * (Dc * Ec) + (size_t)d * Ec;
        const float* xp1 = cw_q + (size_t)(t + 128) * (Dc * Ec) + (size_t)d * Ec;
        #pragma unroll
        for (int q = 0; q < 4; q++) {
            float4 v = ((const float4*)xp0)[q];
            x20 += v.x * v.x; x20 += v.y * v.y; x20 += v.z * v.z; x20 += v.w * v.w;
            xx0[4*q+0] = pk2(-2.0f*v.x, -2.0f*v.x);
            xx0[4*q+1] = pk2(-2.0f*v.y, -2.0f*v.y);
            xx0[4*q+2] = pk2(-2.0f*v.z, -2.0f*v.z);
            xx0[4*q+3] = pk2(-2.0f*v.w, -2.0f*v.w);
        }
        #pragma unroll
        for (int q = 0; q < 4; q++) {
            float4 v = ((const float4*)xp1)[q];
            x21 += v.x * v.x; x21 += v.y * v.y; x21 += v.z * v.z; x21 += v.w * v.w;
            xx1[4*q+0] = pk2(-2.0f*v.x, -2.0f*v.x);
            xx1[4*q+1] = pk2(-2.0f*v.y, -2.0f*v.y);
            xx1[4*q+2] = pk2(-2.0f*v.z, -2.0f*v.z);
            xx1[4*q+3] = pk2(-2.0f*v.w, -2.0f*v.w);
        }
    }

    const unsigned long long X20 = pk2(x20, x20);
    const unsigned long long X21 = pk2(x21, x21);
    const unsigned long long ZZ  = pk2(0.0f, 0.0f);
    const unsigned long long* c2p = (const unsigned long long*)c2f;
    const ulonglong2* cp2 = (const ulonglong2*)cpack;

    float best0 = 3.4e38f, best1 = 3.4e38f;
    int bi0 = 0, bi1 = 0;

    float4* z4 = (float4*)(out + OFF_OH + (size_t)(d * KSPLIT + sp) * ZCHUNK);
    const float4 zf4 = make_float4(0.f, 0.f, 0.f, 0.f);

    for (int seg = 0; seg < 8; seg++) {
        #pragma unroll 2
        for (int pp = 0; pp < 8; pp++) {
            const int p = seg * 8 + pp;
            const ulonglong2* row = cp2 + p * 8;
            unsigned long long a0 = ZZ, a1 = ZZ, a2 = ZZ, a3 = ZZ;
            unsigned long long b0 = ZZ, b1 = ZZ, b2 = ZZ, b3 = ZZ;
            #pragma unroll
            for (int j = 0; j < 4; j++) {
                ulonglong2 u = row[2 * j];
                ulonglong2 w = row[2 * j + 1];
                a0 = f2fma(xx0[4*j+0], u.x, a0);
                a1 = f2fma(xx0[4*j+1], u.y, a1);
                a2 = f2fma(xx0[4*j+2], w.x, a2);
                a3 = f2fma(xx0[4*j+3], w.y, a3);
                b0 = f2fma(xx1[4*j+0], u.x, b0);
                b1 = f2fma(xx1[4*j+1], u.y, b1);
                b2 = f2fma(xx1[4*j+2], w.x, b2);
                b3 = f2fma(xx1[4*j+3], w.y, b3);
            }
            unsigned long long c2v = c2p[p];
            {
                unsigned long long dot  = f2add(f2add(a0, a1), f2add(a2, a3));
                unsigned long long dist = f2add(f2add(X20, c2v), dot);
                float d0, d1; upk2(dist, d0, d1);
                float cd = d0; int ck = 2 * p;
                if (d1 < d0) { cd = d1; ck = 2 * p + 1; }
                if (cd < best0) { best0 = cd; bi0 = ck; }
            }
            {
                unsigned long long dot  = f2add(f2add(b0, b1), f2add(b2, b3));
                unsigned long long dist = f2add(f2add(X21, c2v), dot);
                float d0, d1; upk2(dist, d0, d1);
                float cd = d0; int ck = 2 * p;
                if (d1 < d0) { cd = d1; ck = 2 * p + 1; }
                if (cd < best1) { best1 = cd; bi1 = ck; }
            }
        }
        #pragma unroll
        for (int j = 0; j < 8; j++)
            __stcs(&z4[seg * 1024 + j * 128 + t], zf4);
    }

    const size_t kb = ((size_t)sp * Dc + d) * Bc;
    g_key[kb + t] = ((unsigned long long)orderable(best0) << 32)
                  | (unsigned long long)(sp * KH + bi0);
    g_key[kb + t + 128] = ((unsigned long long)orderable(best1) << 32)
                        | (unsigned long long)(sp * KH + bi1);
}

// =====================================================================
// Kernel 2a: combine split keys -> sidx in both layouts.
// grid = Dc, block = 256 (thread = b). All key loads coalesced.
// =====================================================================
__global__ void __launch_bounds__(256)
vq_combine()
{
    const int d = blockIdx.x;
    const int b = threadIdx.x;

    unsigned long long key = g_key[((size_t)0 * Dc + d) * Bc + b];
    #pragma unroll
    for (int sp = 1; sp < KSPLIT; sp++) {
        unsigned long long k2 = g_key[((size_t)sp * Dc + d) * Bc + b];
        if (k2 < key) key = k2;
    }
    const int idx = (int)(key & 0xFFFFFFFFull);
    g_sidx_db[(size_t)d * Bc + b] = idx;   // coalesced
    g_sidx_bd[(size_t)b * Dc + d] = idx;   // L2 write-merged across blocks
}

// =====================================================================
// Kernel 2b: cw_embed + one_hot scatter. grid = Bc, block = 256 (thread = d).
// embed row per block is a contiguous, fully coalesced 16 KB store.
// =====================================================================
__global__ void __launch_bounds__(256)
vq_embed_oh(const float* __restrict__ codebook,
            float* __restrict__ out)
{
    const int b = blockIdx.x;
    const int d = threadIdx.x;

    const int idx = g_sidx_bd[(size_t)b * Dc + d];   // coalesced

    // one_hot: the single 1.0 for (b, d) (slab pre-zeroed by K1)
    out[OFF_OH + (size_t)b * (Dc * Kc) + (size_t)d * Kc + idx] = 1.0f;

    // cw_embed[b, d*16..]: gather codebook[d][idx], coalesced store
    const float4* ce = (const float4*)(codebook + ((size_t)d * Kc + idx) * Ec);
    float4 v0 = __ldg(ce + 0);
    float4 v1 = __ldg(ce + 1);
    float4 v2 = __ldg(ce + 2);
    float4 v3 = __ldg(ce + 3);
    float4* dst = (float4*)(out + OFF_EMB + (size_t)b * (Dc * Ec) + (size_t)d * Ec);
    dst[0] = v0; dst[1] = v1; dst[2] = v2; dst[3] = v3;
}

// =====================================================================
// Kernel 3: EMA outputs. grid = (Dc, 4), block = 256 (thread = one code k).
// Register accumulation via broadcast scan of sidx — no atomics/barrier/zeroing.
// =====================================================================
__global__ void __launch_bounds__(256)
vq_ema(const float* __restrict__ cw_q,
       const float* __restrict__ codebook,
       const float* __restrict__ ema,
       float* __restrict__ out)
{
    __shared__ int sidx_s[Bc];

    const int d = blockIdx.x;
    const int t = threadIdx.x;
    const int k = blockIdx.y * 256 + t;

    sidx_s[t] = g_sidx_db[(size_t)d * Bc + t];
    __syncthreads();

    float acc[16];
    #pragma unroll
    for (int e = 0; e < 16; e++) acc[e] = 0.f;
    int cnt = 0;

    // scan batches in ascending order (matches reference summation order)
    for (int b = 0; b < Bc; b++) {
        if (sidx_s[b] == k) {
            const float4* xp = (const float4*)(cw_q + ((size_t)b * Dc + d) * Ec);
            #pragma unroll
            for (int q = 0; q < 4; q++) {
                float4 v = xp[q];
                acc[4*q+0] += v.x; acc[4*q+1] += v.y;
                acc[4*q+2] += v.z; acc[4*q+3] += v.w;
            }
            cnt++;
        }
    }

    const float emak = ema[(size_t)d * Kc + k];
    out[OFF_NEC + (size_t)d * Kc + k] = 0.999f * emak + 0.001f * (float)cnt;

    const float inv = 1.0f / (emak + 1e-6f);   // one correctly-rounded div per k
    const float4* cbp = (const float4*)(codebook + ((size_t)d * Kc + k) * Ec);
    float4* ncp = (float4*)(out + OFF_NCB + ((size_t)d * Kc + k) * Ec);
    #pragma unroll
    for (int q = 0; q < 4; q++) {
        float4 c = cbp[q];
        float4 o;
        o.x = 0.999f * c.x + 0.001f * (acc[4*q+0] * inv);
        o.y = 0.999f * c.y + 0.001f * (acc[4*q+1] * inv);
        o.z = 0.999f * c.z + 0.001f * (acc[4*q+2] * inv);
        o.w = 0.999f * c.w + 0.001f * (acc[4*q+3] * inv);
        ncp[q] = o;
    }
}

extern "C" void kernel_launch(void* const* d_in, const int* in_sizes, int n_in,
                              void* d_out, int out_size)
{
    const float* cw_q     = (const float*)d_in[0];
    const float* codebook = (const float*)d_in[1];
    const float* ema      = (const float*)d_in[2];
    float* out            = (float*)d_out;

    vq_argmin_zf<<<dim3(Dc, KSPLIT), 128>>>(cw_q, codebook, out);
    vq_combine<<<Dc, 256>>>();
    vq_embed_oh<<<Bc, 256>>>(codebook, out);
    vq_ema<<<dim3(Dc, 4), 256>>>(cw_q, codebook, ema, out);
}

// round 10
// speedup vs baseline: 1.7566x; 1.1243x over previous
#include <cuda_runtime.h>
#include <cstdint>
#include <cstddef>

// Problem constants
#define Bc 256
#define Dc 256
#define Kc 1024
#define Ec 16
#define KSPLIT 8
#define KH (Kc / KSPLIT)   // 128 codes per argmin block

// Output offsets (floats) within d_out, in reference return order:
// cw_embed (B, D*E), one_hot (B, D, K), new_codebook (D, K, E), new_ema (D, K)
static const size_t OFF_EMB = 0;
static const size_t OFF_OH  = (size_t)Bc * Dc * Ec;                    // 1,048,576
static const size_t OFF_NCB = OFF_OH + (size_t)Bc * Dc * Kc;           // 68,157,440
static const size_t OFF_NEC = OFF_NCB + (size_t)Dc * Kc * Ec;          // 72,351,744

// One_hot zero-fill: 67,108,864 floats / 2048 blocks = 32768 floats per block.
#define ZCHUNK 32768

// Scratch
__device__ unsigned long long g_key[KSPLIT * Dc * Bc];  // packed argmin keys
__device__ int g_sidx_db[Dc * Bc];                      // argmin, [d][b]
__device__ int g_sidx_bd[Bc * Dc];                      // argmin, [b][d]

// ---- packed f32x2 helpers (Blackwell) ----
__device__ __forceinline__ unsigned long long pk2(float a, float b) {
    unsigned long long r;
    asm("mov.b64 %0,{%1,%2};" : "=l"(r) : "f"(a), "f"(b));
    return r;
}
__device__ __forceinline__ void upk2(unsigned long long v, float& a, float& b) {
    asm("mov.b64 {%0,%1},%2;" : "=f"(a), "=f"(b) : "l"(v));
}
__device__ __forceinline__ unsigned long long f2fma(unsigned long long a, unsigned long long b, unsigned long long c) {
    unsigned long long d;
    asm("fma.rn.f32x2 %0,%1,%2,%3;" : "=l"(d) : "l"(a), "l"(b), "l"(c));
    return d;
}
__device__ __forceinline__ unsigned long long f2add(unsigned long long a, unsigned long long b) {
    unsigned long long d;
    asm("add.rn.f32x2 %0,%1,%2;" : "=l"(d) : "l"(a), "l"(b));
    return d;
}

// Map float to an order-preserving uint (no NaNs expected).
__device__ __forceinline__ unsigned int orderable(float f) {
    unsigned int u = __float_as_uint(f);
    return (u & 0x80000000u) ? ~u : (u | 0x80000000u);
}

// =====================================================================
// Kernel 1: argmin over one K-chunk + one_hot zero-fill.
// grid = (Dc, KSPLIT), block = 64. Thread t handles batches t+64r, r=0..3.
// Per k-pair: 8 LDS.128 (broadcast) feed 64 FFMA2 (16 independent chains).
// Zero stores interleaved every 8 k-pairs to spread DRAM writes.
// =====================================================================
__global__ void __launch_bounds__(64, 4)
vq_argmin_zf(const float* __restrict__ cw_q,
             const float* __restrict__ codebook,
             float* __restrict__ out)
{
    // cpack[(k>>1)*32 + e*2 + (k&1)] = codebook[d][sp*KH + k][e]
    __shared__ float cpack[KH * Ec];         // 8 KB
    __shared__ float c2f[KH];                // 0.5 KB (code pairs adjacent)

    const int d  = blockIdx.x;
    const int sp = blockIdx.y;
    const int t  = threadIdx.x;
    const float* cb = codebook + ((size_t)d * Kc + (size_t)sp * KH) * Ec;

    // stage + pack codebook chunk (512 float4s, 8 per thread)
    #pragma unroll
    for (int i = t; i < (KH * Ec) / 4; i += 64) {
        float4 v = ((const float4*)cb)[i];
        int k  = i >> 2;
        int e0 = (i & 3) * 4;
        float* dstp = &cpack[(k >> 1) * 32 + (k & 1)];
        dstp[(e0 + 0) * 2] = v.x;
        dstp[(e0 + 1) * 2] = v.y;
        dstp[(e0 + 2) * 2] = v.z;
        dstp[(e0 + 3) * 2] = v.w;
    }
    __syncthreads();

    // per-k squared norms (2 per thread)
    #pragma unroll
    for (int k = t; k < KH; k += 64) {
        const float* cp = cpack + (k >> 1) * 32 + (k & 1);
        float s = 0.f;
        #pragma unroll
        for (int e = 0; e < 16; e++) { float c = cp[e * 2]; s += c * c; }
        c2f[k] = s;
    }
    __syncthreads();

    // load x for 4 batches; pack (-2x) duplicates (exactly -2 * original chain)
    unsigned long long xx[4][16];
    unsigned long long X2[4];
    #pragma unroll
    for (int r = 0; r < 4; r++) {
        const float* xp = cw_q + (size_t)(t + 64 * r) * (Dc * Ec) + (size_t)d * Ec;
        float x2 = 0.f;
        #pragma unroll
        for (int q = 0; q < 4; q++) {
            float4 v = ((const float4*)xp)[q];
            x2 += v.x * v.x; x2 += v.y * v.y; x2 += v.z * v.z; x2 += v.w * v.w;
            xx[r][4*q+0] = pk2(-2.0f*v.x, -2.0f*v.x);
            xx[r][4*q+1] = pk2(-2.0f*v.y, -2.0f*v.y);
            xx[r][4*q+2] = pk2(-2.0f*v.z, -2.0f*v.z);
            xx[r][4*q+3] = pk2(-2.0f*v.w, -2.0f*v.w);
        }
        X2[r] = pk2(x2, x2);
    }

    const unsigned long long ZZ = pk2(0.0f, 0.0f);
    const unsigned long long* c2p = (const unsigned long long*)c2f;
    const ulonglong2* cp2 = (const ulonglong2*)cpack;

    float best[4] = {3.4e38f, 3.4e38f, 3.4e38f, 3.4e38f};
    int   bi[4]   = {0, 0, 0, 0};

    float4* z4 = (float4*)(out + OFF_OH + (size_t)(d * KSPLIT + sp) * ZCHUNK);
    const float4 zf4 = make_float4(0.f, 0.f, 0.f, 0.f);

    // KH/2 = 64 k-pairs = 8 segments x 8 pairs; 16 zero-float4 per thread per seg
    for (int seg = 0; seg < 8; seg++) {
        #pragma unroll 1
        for (int pp = 0; pp < 8; pp++) {
            const int p = seg * 8 + pp;
            const ulonglong2* row = cp2 + p * 8;
            unsigned long long acc[4][4];
            #pragma unroll
            for (int r = 0; r < 4; r++) {
                acc[r][0] = ZZ; acc[r][1] = ZZ; acc[r][2] = ZZ; acc[r][3] = ZZ;
            }
            #pragma unroll
            for (int j = 0; j < 4; j++) {
                ulonglong2 u = row[2 * j];
                ulonglong2 w = row[2 * j + 1];
                #pragma unroll
                for (int r = 0; r < 4; r++) {
                    acc[r][0] = f2fma(xx[r][4*j+0], u.x, acc[r][0]);
                    acc[r][1] = f2fma(xx[r][4*j+1], u.y, acc[r][1]);
                    acc[r][2] = f2fma(xx[r][4*j+2], w.x, acc[r][2]);
                    acc[r][3] = f2fma(xx[r][4*j+3], w.y, acc[r][3]);
                }
            }
            const unsigned long long c2v = c2p[p];
            #pragma unroll
            for (int r = 0; r < 4; r++) {
                unsigned long long dot  = f2add(f2add(acc[r][0], acc[r][1]),
                                                f2add(acc[r][2], acc[r][3]));
                unsigned long long dist = f2add(f2add(X2[r], c2v), dot);
                float d0, d1; upk2(dist, d0, d1);
                float cd = d0; int ck = 2 * p;
                if (d1 < d0) { cd = d1; ck = 2 * p + 1; }   // first-min semantics
                if (cd < best[r]) { best[r] = cd; bi[r] = ck; }
            }
        }
        // interleaved one_hot zero-fill: 16 float4 per thread per segment
        #pragma unroll
        for (int j = 0; j < 16; j++)
            __stcs(&z4[seg * 1024 + j * 64 + t], zf4);
    }

    // pack (orderable dist, global k): min over keys == first-occurrence argmin
    const size_t kb = ((size_t)sp * Dc + d) * Bc;
    #pragma unroll
    for (int r = 0; r < 4; r++) {
        g_key[kb + t + 64 * r] = ((unsigned long long)orderable(best[r]) << 32)
                               | (unsigned long long)(sp * KH + bi[r]);
    }
}

// =====================================================================
// Kernel 2a: combine split keys -> sidx in both layouts.
// grid = Dc, block = 256 (thread = b). All key loads coalesced.
// =====================================================================
__global__ void __launch_bounds__(256)
vq_combine()
{
    const int d = blockIdx.x;
    const int b = threadIdx.x;

    unsigned long long key = g_key[((size_t)0 * Dc + d) * Bc + b];
    #pragma unroll
    for (int sp = 1; sp < KSPLIT; sp++) {
        unsigned long long k2 = g_key[((size_t)sp * Dc + d) * Bc + b];
        if (k2 < key) key = k2;
    }
    const int idx = (int)(key & 0xFFFFFFFFull);
    g_sidx_db[(size_t)d * Bc + b] = idx;   // coalesced
    g_sidx_bd[(size_t)b * Dc + d] = idx;   // L2 write-merged across blocks
}

// =====================================================================
// Kernel 2b: cw_embed + one_hot scatter. grid = Bc, block = 256 (thread = d).
// =====================================================================
__global__ void __launch_bounds__(256)
vq_embed_oh(const float* __restrict__ codebook,
            float* __restrict__ out)
{
    const int b = blockIdx.x;
    const int d = threadIdx.x;

    const int idx = g_sidx_bd[(size_t)b * Dc + d];   // coalesced

    // one_hot: the single 1.0 for (b, d) (slab pre-zeroed by K1)
    out[OFF_OH + (size_t)b * (Dc * Kc) + (size_t)d * Kc + idx] = 1.0f;

    // cw_embed[b, d*16..]: gather codebook[d][idx] (L2-resident), coalesced store
    const float4* ce = (const float4*)(codebook + ((size_t)d * Kc + idx) * Ec);
    float4 v0 = __ldg(ce + 0);
    float4 v1 = __ldg(ce + 1);
    float4 v2 = __ldg(ce + 2);
    float4 v3 = __ldg(ce + 3);
    float4* dst = (float4*)(out + OFF_EMB + (size_t)b * (Dc * Ec) + (size_t)d * Ec);
    dst[0] = v0; dst[1] = v1; dst[2] = v2; dst[3] = v3;
}

// =====================================================================
// Kernel 3: EMA outputs via smem atomic scatter. grid = Dc, block = 256
// (thread = b). acc layout [e][Kc+1] (padded -> conflict-free banks).
// =====================================================================
#define KP (Kc + 1)
#define K3_ACC_BYTES (Ec * KP * 4)                         // 65600
#define K3_SMEM (K3_ACC_BYTES + Kc * 4 + Kc * 4)           // + scnt + sinv = 73792

extern __shared__ unsigned char smemE[];

__global__ void __launch_bounds__(256)
vq_ema(const float* __restrict__ cw_q,
       const float* __restrict__ codebook,
       const float* __restrict__ ema,
       float* __restrict__ out)
{
    float* acc  = (float*)smemE;                            // [Ec][KP]
    int*   scnt = (int*)(smemE + K3_ACC_BYTES);             // [Kc]
    float* sinv = (float*)(smemE + K3_ACC_BYTES + Kc * 4);  // [Kc]

    const int d = blockIdx.x;
    const int t = threadIdx.x;
    const int b = t;

    const int idx = g_sidx_db[(size_t)d * Bc + b];   // coalesced

    // zero acc + scnt
    #pragma unroll
    for (int i = t; i < Ec * KP; i += 256) acc[i] = 0.f;
    #pragma unroll
    for (int i = t; i < Kc; i += 256) scnt[i] = 0;
    __syncthreads();

    atomicAdd(&scnt[idx], 1);

    // scatter x into acc (random idx -> spread banks)
    {
        const float4* xp = (const float4*)(cw_q + ((size_t)b * Dc + d) * Ec);
        #pragma unroll
        for (int q = 0; q < 4; q++) {
            float4 v = xp[q];
            atomicAdd(&acc[(4*q+0) * KP + idx], v.x);
            atomicAdd(&acc[(4*q+1) * KP + idx], v.y);
            atomicAdd(&acc[(4*q+2) * KP + idx], v.z);
            atomicAdd(&acc[(4*q+3) * KP + idx], v.w);
        }
    }
    __syncthreads();

    // per-k: new_ema_counts + hoisted reciprocal (4 divides per thread)
    const float* emad = ema + (size_t)d * Kc;
    #pragma unroll
    for (int k = t; k < Kc; k += 256) {
        float emak = emad[k];
        out[OFF_NEC + (size_t)d * Kc + k] = 0.999f * emak + 0.001f * (float)scnt[k];
        sinv[k] = 1.0f / (emak + 1e-6f);
    }
    __syncthreads();

    // new_codebook: fully coalesced read/modify/write
    {
        const float* cbd = codebook + (size_t)d * (Kc * Ec);
        float* ncb = out + OFF_NCB + (size_t)d * (Kc * Ec);
        #pragma unroll 4
        for (int j = 0; j < (Kc * Ec) / 256; j++) {
            int i = t + 256 * j;
            int k = i >> 4;
            int e = i & 15;
            ncb[i] = 0.999f * cbd[i] + 0.001f * (acc[e * KP + k] * sinv[k]);
        }
    }
}

extern "C" void kernel_launch(void* const* d_in, const int* in_sizes, int n_in,
                              void* d_out, int out_size)
{
    const float* cw_q     = (const float*)d_in[0];
    const float* codebook = (const float*)d_in[1];
    const float* ema      = (const float*)d_in[2];
    float* out            = (float*)d_out;

    cudaFuncSetAttribute(vq_ema, cudaFuncAttributeMaxDynamicSharedMemorySize, K3_SMEM);

    vq_argmin_zf<<<dim3(Dc, KSPLIT), 64>>>(cw_q, codebook, out);
    vq_combine<<<Dc, 256>>>();
    vq_embed_oh<<<Bc, 256>>>(codebook, out);
    vq_ema<<<dim3(Dc), 256, K3_SMEM>>>(cw_q, codebook, ema, out);
}